// round 10
// baseline (speedup 1.0000x reference)
#include <cuda_runtime.h>
#include <math.h>
#include <stdint.h>

// Problem constants
#define BB   16
#define CC   128
#define HW   4096          // 64*64
#define NN   65536         // BB*HW
#define KK   1024
#define Q_ELEMS (BB*CC*HW) // 1048576
#define OUT_IDX_OFF Q_ELEMS
#define OUT_SCAL_OFF (Q_ELEMS + NN)

#define M_CTA   128
#define CAP     32
#define KCSCALE 130047.0f  // int8 scale for codebook (|c| <= 2^-10 -> |q|<=127)

// k_screen dynamic smem layout (bytes)
#define ZEX_OFF  0         // f32 zex[128][129]  66048 (exact z, persists for rescore)
#define ZQ_OFF   66048     // u32 zq [32][128]   16384 (packed int8 z, [kg][row])
#define CQ_OFF   82432     // u32 cq [32][128]   16384 (packed int8 codes, [kg][code])
#define CCS_OFF  98816     // f32 ccs[1024]      4096
#define CAND_OFF 102912    // u16 cand[128][32]  8192   (f32 red[256] during zmax pass)
#define CNT_OFF  111104    // s32 cnt[128]       512
#define SM_DYN   111616

// Scratch (no allocation allowed)
__device__ uint32_t g_cbqT[32 * KK];     // int8-packed codebook, transposed [kg][code]
__device__ float  g_cc[KK];              // ||c_k||^2 (fp32 sequential chain)
__device__ int    g_idx[NN];             // argmin indices
__device__ int    g_counts[KK];          // code usage counts
__device__ double g_partial[NN/64];      // per-block loss partials

// ---------------------------------------------------------------------------
// K1: codebook -> packed int8 (transposed), row norms (ref chain), zero counts
// ---------------------------------------------------------------------------
__global__ void k_prep(const float* __restrict__ cb) {
    int g = blockIdx.x * blockDim.x + threadIdx.x;
    if (g < 32 * KK) {
        int code = g >> 5, kg = g & 31;
        float4 v = *(const float4*)(cb + code * CC + kg * 4);
        int q0 = __float2int_rn(v.x * KCSCALE);
        int q1 = __float2int_rn(v.y * KCSCALE);
        int q2 = __float2int_rn(v.z * KCSCALE);
        int q3 = __float2int_rn(v.w * KCSCALE);
        uint32_t p = (uint32_t)(q0 & 255) | ((uint32_t)(q1 & 255) << 8)
                   | ((uint32_t)(q2 & 255) << 16) | ((uint32_t)(q3 & 255) << 24);
        g_cbqT[kg * KK + code] = p;
    }
    if (g < KK) {
        const float* row = cb + g * CC;
        float s = 0.f;
        for (int i = 0; i < CC; i++)
            s = __fadd_rn(s, __fmul_rn(row[i], row[i]));
        g_cc[g] = s;
        g_counts[g] = 0;
    }
}

// ---------------------------------------------------------------------------
// K2: int8 DP4A screening + exact fp32 rescoring (fused).
// Grid 512 CTAs x 256 threads. CTA: 128 rows vs all 1024 codes.
// Thread micro-tile: 8 rows x 8 codes (rows rg*4..+3 and 64+rg*4..+3;
// codes cg*4..+3 and 64+cg*4..+3 within each 128-code chunk).
// Screening score s~ = cc + lam*dot_int  (lam = -2/(scale_z*scale_c)); margin
// is a worst-case bound from the actual quantization steps, so the candidate
// set provably contains the true argmin. Rescore = bit-exact R2 chain.
// ---------------------------------------------------------------------------
__global__ __launch_bounds__(256, 2)
void k_screen(const float* __restrict__ z, const float* __restrict__ cb,
              float* __restrict__ out_idx_f) {
    extern __shared__ char smem[];
    float*    zex  = (float*)(smem + ZEX_OFF);
    uint32_t* zq   = (uint32_t*)(smem + ZQ_OFF);
    uint32_t* cq   = (uint32_t*)(smem + CQ_OFF);
    float*    ccs  = (float*)(smem + CCS_OFF);
    uint16_t* cand = (uint16_t*)(smem + CAND_OFF);
    float*    redf = (float*)(smem + CAND_OFF);   // reused before cand
    int*      cnt  = (int*)(smem + CNT_OFF);

    const int tid  = threadIdx.x;
    const int cg   = tid & 15;
    const int rg   = tid >> 4;
    const int n0   = blockIdx.x * M_CTA;
    const int b    = n0 >> 12;
    const int hw0  = n0 & 4095;
    const float* zb = z + (size_t)b * CC * HW + hw0;

    // Pass 1: stage exact z into zex[row][129] + local absmax
    float lmax = 0.f;
    for (int i = tid; i < 128 * 128; i += 256) {
        int k = i >> 7, hw = i & 127;
        float v = zb[k * HW + hw];
        zex[hw * 129 + k] = v;
        lmax = fmaxf(lmax, fabsf(v));
    }
    redf[tid] = lmax;
    __syncthreads();
    #pragma unroll
    for (int s = 128; s > 0; s >>= 1) {
        if (tid < s) redf[tid] = fmaxf(redf[tid], redf[tid + s]);
        __syncthreads();
    }
    const float zmax = fmaxf(redf[0], 1e-20f);
    __syncthreads();   // everyone has zmax; redf area free for cand now

    const float scale_z = 126.9999f / zmax;
    const float qz = zmax / 253.0f;
    // margin = 4 * worst-case pair error of (cc - 2*z.c) vs screen score
    const float margin = 4.0f * (qz * 0.1251f + 3.9e-6f * (128.0f * zmax))
                       + 1e-5f;
    const float lam = -2.0f / (scale_z * KCSCALE);

    // Pass 2: quantize zex -> zq[kg][row], init cnt, load ccs
    if (tid < 128) cnt[tid] = 0;
    for (int i = tid; i < KK; i += 256) ccs[i] = g_cc[i];
    for (int i = tid; i < 32 * 128; i += 256) {
        int kg = i >> 7, row = i & 127;
        const float* zr = zex + row * 129 + kg * 4;
        int q0 = __float2int_rn(zr[0] * scale_z);
        int q1 = __float2int_rn(zr[1] * scale_z);
        int q2 = __float2int_rn(zr[2] * scale_z);
        int q3 = __float2int_rn(zr[3] * scale_z);
        zq[kg * 128 + row] = (uint32_t)(q0 & 255) | ((uint32_t)(q1 & 255) << 8)
                           | ((uint32_t)(q2 & 255) << 16) | ((uint32_t)(q3 & 255) << 24);
    }

    const int rowL = rg * 4, rowH = 64 + rg * 4;
    float tminL[4], tminH[4];
    #pragma unroll
    for (int r = 0; r < 4; r++) { tminL[r] = 3.4e38f; tminH[r] = 3.4e38f; }

    for (int c = 0; c < 8; c++) {
        __syncthreads();   // prev chunk compute done (and zq/cnt ready at c=0)
        // Stage codebook chunk: cq[kg][code] = g_cbqT[kg*1024 + c*128 + code]
        for (int i = tid; i < 32 * 128; i += 256) {
            int kg = i >> 7, cd = i & 127;
            cq[kg * 128 + cd] = g_cbqT[kg * KK + c * 128 + cd];
        }
        __syncthreads();

        int aLL[4][4], aLH[4][4], aHL[4][4], aHH[4][4];
        #pragma unroll
        for (int r = 0; r < 4; r++)
            #pragma unroll
            for (int j = 0; j < 4; j++) {
                aLL[r][j] = 0; aLH[r][j] = 0; aHL[r][j] = 0; aHH[r][j] = 0;
            }

        const uint32_t* zpL = zq + rowL;
        const uint32_t* zpH = zq + rowH;
        const uint32_t* cpL = cq + cg * 4;
        const uint32_t* cpH = cq + 64 + cg * 4;

        #pragma unroll 4
        for (int kg = 0; kg < 32; kg++) {
            uint4 aL = *(const uint4*)(zpL + kg * 128);
            uint4 aH = *(const uint4*)(zpH + kg * 128);
            uint4 bL = *(const uint4*)(cpL + kg * 128);
            uint4 bH = *(const uint4*)(cpH + kg * 128);
            int av[4] = {(int)aL.x, (int)aL.y, (int)aL.z, (int)aL.w};
            int aw[4] = {(int)aH.x, (int)aH.y, (int)aH.z, (int)aH.w};
            int bv[4] = {(int)bL.x, (int)bL.y, (int)bL.z, (int)bL.w};
            int bw[4] = {(int)bH.x, (int)bH.y, (int)bH.z, (int)bH.w};
            #pragma unroll
            for (int r = 0; r < 4; r++) {
                #pragma unroll
                for (int j = 0; j < 4; j++) {
                    aLL[r][j] = __dp4a(av[r], bv[j], aLL[r][j]);
                    aLH[r][j] = __dp4a(av[r], bw[j], aLH[r][j]);
                    aHL[r][j] = __dp4a(aw[r], bv[j], aHL[r][j]);
                    aHH[r][j] = __dp4a(aw[r], bw[j], aHH[r][j]);
                }
            }
        }

        // Epilogue: scores, conservative running-min threshold, append
        const int codeL0 = c * 128 + cg * 4;
        const int codeH0 = codeL0 + 64;
        float4 ccL4 = *(const float4*)(ccs + codeL0);
        float4 ccH4 = *(const float4*)(ccs + codeH0);
        float ccL[4] = {ccL4.x, ccL4.y, ccL4.z, ccL4.w};
        float ccH[4] = {ccH4.x, ccH4.y, ccH4.z, ccH4.w};
        #pragma unroll
        for (int r = 0; r < 4; r++) {
            float sLL[4], sLH[4], sHL[4], sHH[4];
            #pragma unroll
            for (int j = 0; j < 4; j++) {
                sLL[j] = fmaf((float)aLL[r][j], lam, ccL[j]);
                sLH[j] = fmaf((float)aLH[r][j], lam, ccH[j]);
                sHL[j] = fmaf((float)aHL[r][j], lam, ccL[j]);
                sHH[j] = fmaf((float)aHH[r][j], lam, ccH[j]);
            }
            float mL = fminf(fminf(fminf(sLL[0], sLL[1]), fminf(sLL[2], sLL[3])),
                             fminf(fminf(sLH[0], sLH[1]), fminf(sLH[2], sLH[3])));
            float mH = fminf(fminf(fminf(sHL[0], sHL[1]), fminf(sHL[2], sHL[3])),
                             fminf(fminf(sHH[0], sHH[1]), fminf(sHH[2], sHH[3])));
            #pragma unroll
            for (int k = 1; k < 16; k <<= 1) {
                mL = fminf(mL, __shfl_xor_sync(0xffffffffu, mL, k));
                mH = fminf(mH, __shfl_xor_sync(0xffffffffu, mH, k));
            }
            tminL[r] = fminf(tminL[r], mL);
            tminH[r] = fminf(tminH[r], mH);
            float thL = tminL[r] + margin, thH = tminH[r] + margin;
            int rL = rowL + r, rH = rowH + r;
            #pragma unroll
            for (int j = 0; j < 4; j++) {
                if (sLL[j] < thL) { int p = atomicAdd(&cnt[rL], 1); if (p < CAP) cand[rL*CAP+p] = (uint16_t)(codeL0+j); }
                if (sLH[j] < thL) { int p = atomicAdd(&cnt[rL], 1); if (p < CAP) cand[rL*CAP+p] = (uint16_t)(codeH0+j); }
                if (sHL[j] < thH) { int p = atomicAdd(&cnt[rH], 1); if (p < CAP) cand[rH*CAP+p] = (uint16_t)(codeL0+j); }
                if (sHH[j] < thH) { int p = atomicAdd(&cnt[rH], 1); if (p < CAP) cand[rH*CAP+p] = (uint16_t)(codeH0+j); }
            }
        }
    }
    __syncthreads();

    // ---- Exact rescoring (zex still resident) ----
    if (tid < 128) {
        const float* zr = zex + tid * 129;
        // S_z: strictly sequential fp32 chain (matches ref jnp.sum(z*z))
        float sz = 0.f;
        for (int k = 0; k < CC; k++)
            sz = __fadd_rn(sz, __fmul_rn(zr[k], zr[k]));

        int nc = cnt[tid];
        float best = 3.4e38f;
        int   bidx = 0x7fffffff;
        if (nc <= CAP) {
            for (int i = 0; i < nc; i++) {
                int code = cand[tid * CAP + i];
                const float* cr = cb + code * CC;
                float gacc = 0.f;
                #pragma unroll 8
                for (int k = 0; k < CC; k++) gacc = fmaf(zr[k], cr[k], gacc);
                float d2 = __fadd_rn(__fsub_rn(sz, __fmul_rn(2.f, gacc)), ccs[code]);
                if (d2 < best || (d2 == best && code < bidx)) { best = d2; bidx = code; }
            }
        } else {
            // overflow fallback (rare): exact ascending scan of all codes
            for (int code = 0; code < KK; code++) {
                const float* cr = cb + code * CC;
                float gacc = 0.f;
                #pragma unroll 8
                for (int k = 0; k < CC; k++) gacc = fmaf(zr[k], cr[k], gacc);
                float d2 = __fadd_rn(__fsub_rn(sz, __fmul_rn(2.f, gacc)), ccs[code]);
                if (d2 < best) { best = d2; bidx = code; }
            }
        }
        g_idx[n0 + tid] = bidx;
        out_idx_f[n0 + tid] = (float)bidx;
    }
}

// ---------------------------------------------------------------------------
// K3: gather codebook rows, write quantized, loss partials, counts.
// ---------------------------------------------------------------------------
__global__ __launch_bounds__(256)
void k_quant(const float* __restrict__ z, const float* __restrict__ cb,
             float* __restrict__ out_q) {
    __shared__ int   idx_s[64];
    __shared__ float qs[64][129];
    __shared__ double red[256];

    const int tid = threadIdx.x;
    const int n0  = blockIdx.x * 64;
    const int b   = n0 >> 12;
    const int hw0 = n0 & 4095;

    if (tid < 64) {
        int idx = g_idx[n0 + tid];
        idx_s[tid] = idx;
        atomicAdd(&g_counts[idx], 1);
    }
    __syncthreads();

    for (int g = tid; g < 64 * 128; g += 256) {
        int hw = g >> 7, k = g & 127;
        qs[hw][k] = cb[idx_s[hw] * CC + k];
    }
    __syncthreads();

    const float* zb = z     + (size_t)b * CC * HW + hw0;
    float*       ob = out_q + (size_t)b * CC * HW + hw0;
    const int hw = tid & 63;
    const int c0 = tid >> 6;

    double acc = 0.0;
    #pragma unroll 8
    for (int i = 0; i < 32; i++) {
        int c = c0 + i * 4;
        float zv = zb[c * HW + hw];
        float qv = qs[hw][c];
        ob[c * HW + hw] = __fadd_rn(zv, __fsub_rn(qv, zv));
        float d = __fsub_rn(zv, qv);
        acc += (double)d * (double)d;
    }

    red[tid] = acc;
    __syncthreads();
    #pragma unroll
    for (int s = 128; s > 0; s >>= 1) {
        if (tid < s) red[tid] += red[tid + s];
        __syncthreads();
    }
    if (tid == 0) g_partial[blockIdx.x] = red[0];
}

// ---------------------------------------------------------------------------
// K4: finalize — vq_loss and perplexity
// ---------------------------------------------------------------------------
__global__ __launch_bounds__(256)
void k_final(float* __restrict__ out) {
    __shared__ double red[256];
    const int tid = threadIdx.x;

    double a = 0.0;
    for (int i = tid; i < NN/64; i += 256) a += g_partial[i];
    red[tid] = a;
    __syncthreads();
    #pragma unroll
    for (int s = 128; s > 0; s >>= 1) {
        if (tid < s) red[tid] += red[tid + s];
        __syncthreads();
    }
    if (tid == 0) {
        double mse = red[0] / (double)Q_ELEMS;
        float m = (float)mse;
        out[OUT_SCAL_OFF + 0] = __fadd_rn(m, 0.25f * m);
    }
    __syncthreads();

    double e = 0.0;
    for (int i = tid; i < KK; i += 256) {
        float p = (float)g_counts[i] / 65536.0f;
        float term = p * logf(p + 1e-10f);
        e += (double)term;
    }
    red[tid] = e;
    __syncthreads();
    #pragma unroll
    for (int s = 128; s > 0; s >>= 1) {
        if (tid < s) red[tid] += red[tid + s];
        __syncthreads();
    }
    if (tid == 0)
        out[OUT_SCAL_OFF + 1] = expf((float)(-red[0]));
}

// ---------------------------------------------------------------------------
extern "C" void kernel_launch(void* const* d_in, const int* in_sizes, int n_in,
                              void* d_out, int out_size) {
    const float* z  = (const float*)d_in[0];  // [16,128,64,64]
    const float* cb = (const float*)d_in[1];  // [1024,128]
    float* out = (float*)d_out;               // [quantized | indices | vq | ppl]

    static bool attr_set = false;
    if (!attr_set) {
        cudaFuncSetAttribute(k_screen, cudaFuncAttributeMaxDynamicSharedMemorySize,
                             SM_DYN);
        attr_set = true;
    }

    k_prep  <<<512, 256>>>(cb);
    k_screen<<<NN / M_CTA, 256, SM_DYN>>>(z, cb, out + OUT_IDX_OFF);
    k_quant <<<NN / 64, 256>>>(z, cb, out);
    k_final <<<1, 256>>>(out);
}

// round 11
// speedup vs baseline: 4.7852x; 4.7852x over previous
#include <cuda_runtime.h>
#include <math.h>
#include <stdint.h>

// Problem constants
#define BB   16
#define CC   128
#define HW   4096          // 64*64
#define NN   65536         // BB*HW
#define KK   1024
#define Q_ELEMS (BB*CC*HW) // 1048576
#define OUT_IDX_OFF Q_ELEMS
#define OUT_SCAL_OFF (Q_ELEMS + NN)

#define M_CTA   128
#define CAP     32
#define KCSCALE 130047.0f  // int8 scale for codebook (|c| <= 2^-10 -> |q|<=127)

// k_screen dynamic smem layout (bytes)
#define ZEX_OFF  0         // f32 zex[128][129]  66048 (exact z, persists for rescore)
#define ZQ_OFF   66048     // u32 zq [32][128]   16384 (packed int8 z, [kg][row])
#define CQ_OFF   82432     // u32 cq [32][128]   16384 (packed int8 codes, [kg][code])
#define CCS_OFF  98816     // f32 ccs[1024]      4096
#define CAND_OFF 102912    // u16 cand[128][32]  8192  (f32 red[512] early, pre-cand)
#define CNT_OFF  111104    // s32 cnt[128]       512
#define MARG_OFF 111616    // f32 marg2[128]     512   (2*m_r + slop)
#define SM_DYN   112128

// Scratch (no allocation allowed)
__device__ uint32_t g_cbqT[32 * KK];     // int8-packed codebook, transposed [kg][code]
__device__ float  g_cc[KK];              // ||c_k||^2 (fp32 sequential chain)
__device__ float  g_U[KK];               // ||c_hat|| + ||eps_c||  per code
__device__ float  g_V[KK];               // ||eps_c||              per code
__device__ int    g_idx[NN];             // argmin indices
__device__ int    g_counts[KK];          // code usage counts
__device__ double g_partial[NN/64];      // per-block loss partials

// ---------------------------------------------------------------------------
// K1: codebook -> packed int8 (transposed), row norms (ref chain),
// quantization-residual norms, zero counts
// ---------------------------------------------------------------------------
__global__ void k_prep(const float* __restrict__ cb) {
    int g = blockIdx.x * blockDim.x + threadIdx.x;
    if (g < 32 * KK) {
        int code = g >> 5, kg = g & 31;
        float4 v = *(const float4*)(cb + code * CC + kg * 4);
        int q0 = __float2int_rn(v.x * KCSCALE);
        int q1 = __float2int_rn(v.y * KCSCALE);
        int q2 = __float2int_rn(v.z * KCSCALE);
        int q3 = __float2int_rn(v.w * KCSCALE);
        uint32_t p = (uint32_t)(q0 & 255) | ((uint32_t)(q1 & 255) << 8)
                   | ((uint32_t)(q2 & 255) << 16) | ((uint32_t)(q3 & 255) << 24);
        g_cbqT[kg * KK + code] = p;
    }
    if (g < KK) {
        const float* row = cb + g * CC;
        float s = 0.f;
        for (int i = 0; i < CC; i++)
            s = __fadd_rn(s, __fmul_rn(row[i], row[i]));
        g_cc[g] = s;
        // exact dequant / residual norms
        float sc2 = 0.f, se2 = 0.f;
        const float inv = 1.0f / KCSCALE;
        for (int i = 0; i < CC; i++) {
            float v = row[i];
            int   q = __float2int_rn(v * KCSCALE);
            float ch = (float)q * inv;
            float e  = v - ch;
            sc2 = fmaf(ch, ch, sc2);
            se2 = fmaf(e, e, se2);
        }
        float nc = sqrtf(sc2), ne = sqrtf(se2);
        g_U[g] = nc + ne;
        g_V[g] = ne;
        g_counts[g] = 0;
    }
}

// ---------------------------------------------------------------------------
// K2: int8 DP4A screening + exact fp32 rescoring (fused).
// Grid 512 CTAs x 256 threads. CTA: 128 rows vs all 1024 codes.
// Screening score s~ = cc + lam*dot_int. Per-row rigorous margin from exact
// realized residual norms (Cauchy-Schwarz):
//   |s - s~| <= m_r = 2*(||eps_z||*maxU + ||z_hat||*maxV)
// keep code if s~ < runmin + 2*m_r + slop  -> provable argmin superset.
// Rescore = bit-exact R2 chain d2 = fl(fl(S_z - 2G) + S_c).
// ---------------------------------------------------------------------------
__global__ __launch_bounds__(256, 2)
void k_screen(const float* __restrict__ z, const float* __restrict__ cb,
              float* __restrict__ out_idx_f) {
    extern __shared__ char smem[];
    float*    zex   = (float*)(smem + ZEX_OFF);
    uint32_t* zq    = (uint32_t*)(smem + ZQ_OFF);
    uint32_t* cq    = (uint32_t*)(smem + CQ_OFF);
    float*    ccs   = (float*)(smem + CCS_OFF);
    uint16_t* cand  = (uint16_t*)(smem + CAND_OFF);
    float*    redf  = (float*)(smem + CAND_OFF);   // 512 floats, pre-cand only
    int*      cnt   = (int*)(smem + CNT_OFF);
    float*    marg2 = (float*)(smem + MARG_OFF);

    const int tid  = threadIdx.x;
    const int cg   = tid & 15;
    const int rg   = tid >> 4;
    const int n0   = blockIdx.x * M_CTA;
    const int b    = n0 >> 12;
    const int hw0  = n0 & 4095;
    const float* zb = z + (size_t)b * CC * HW + hw0;

    // Pass 1: stage exact z into zex[row][129] + local absmax
    float lmax = 0.f;
    for (int i = tid; i < 128 * 128; i += 256) {
        int k = i >> 7, hw = i & 127;
        float v = zb[k * HW + hw];
        zex[hw * 129 + k] = v;
        lmax = fmaxf(lmax, fabsf(v));
    }
    redf[tid] = lmax;
    __syncthreads();
    #pragma unroll
    for (int s = 128; s > 0; s >>= 1) {
        if (tid < s) redf[tid] = fmaxf(redf[tid], redf[tid + s]);
        __syncthreads();
    }
    const float zmax = fmaxf(redf[0], 1e-20f);
    __syncthreads();

    const float scale_z = 126.9999f / zmax;
    const float inv_sz  = 1.0f / scale_z;
    const float lam = -2.0f / (scale_z * KCSCALE);

    // Pass 2: quantize zex -> zq[kg][row]; init cnt; load ccs; partial maxU/V
    if (tid < 128) cnt[tid] = 0;
    for (int i = tid; i < KK; i += 256) ccs[i] = g_cc[i];
    float mu = 0.f, mv = 0.f;
    for (int i = tid; i < KK; i += 256) {
        mu = fmaxf(mu, g_U[i]);
        mv = fmaxf(mv, g_V[i]);
    }
    for (int i = tid; i < 32 * 128; i += 256) {
        int kg = i >> 7, row = i & 127;
        const float* zr = zex + row * 129 + kg * 4;
        int q0 = __float2int_rn(zr[0] * scale_z);
        int q1 = __float2int_rn(zr[1] * scale_z);
        int q2 = __float2int_rn(zr[2] * scale_z);
        int q3 = __float2int_rn(zr[3] * scale_z);
        zq[kg * 128 + row] = (uint32_t)(q0 & 255) | ((uint32_t)(q1 & 255) << 8)
                           | ((uint32_t)(q2 & 255) << 16) | ((uint32_t)(q3 & 255) << 24);
    }
    __syncthreads();
    redf[tid] = mu; redf[256 + tid] = mv;
    __syncthreads();
    #pragma unroll
    for (int s = 128; s > 0; s >>= 1) {
        if (tid < s) {
            redf[tid] = fmaxf(redf[tid], redf[tid + s]);
            redf[256 + tid] = fmaxf(redf[256 + tid], redf[256 + s + tid]);
        }
        __syncthreads();
    }
    const float maxU = redf[0], maxV = redf[256];
    __syncthreads();

    // Pass 3 (tid<128): per-row exact residual norms -> margin
    if (tid < 128) {
        const float* zr = zex + tid * 129;
        float se2 = 0.f, sh2 = 0.f;
        for (int k = 0; k < CC; k++) {
            float v = zr[k];
            int   q = __float2int_rn(v * scale_z);   // identical to quant pass
            float zh = (float)q * inv_sz;
            float e  = v - zh;
            se2 = fmaf(e, e, se2);
            sh2 = fmaf(zh, zh, sh2);
        }
        float m = 2.0f * (sqrtf(se2) * maxU + sqrtf(sh2) * maxV);
        marg2[tid] = 2.0f * m + 3e-5f;   // 2m for both-sided bound + d2-chain slop
    }
    __syncthreads();

    const int rowL = rg * 4, rowH = 64 + rg * 4;
    float mgL[4], mgH[4], tminL[4], tminH[4];
    #pragma unroll
    for (int r = 0; r < 4; r++) {
        mgL[r] = marg2[rowL + r];
        mgH[r] = marg2[rowH + r];
        tminL[r] = 3.4e38f; tminH[r] = 3.4e38f;
    }

    for (int c = 0; c < 8; c++) {
        __syncthreads();
        // Stage codebook chunk: cq[kg][code] = g_cbqT[kg*1024 + c*128 + code]
        for (int i = tid; i < 32 * 128; i += 256) {
            int kg = i >> 7, cd = i & 127;
            cq[kg * 128 + cd] = g_cbqT[kg * KK + c * 128 + cd];
        }
        __syncthreads();

        int aLL[4][4], aLH[4][4], aHL[4][4], aHH[4][4];
        #pragma unroll
        for (int r = 0; r < 4; r++)
            #pragma unroll
            for (int j = 0; j < 4; j++) {
                aLL[r][j] = 0; aLH[r][j] = 0; aHL[r][j] = 0; aHH[r][j] = 0;
            }

        const uint32_t* zpL = zq + rowL;
        const uint32_t* zpH = zq + rowH;
        const uint32_t* cpL = cq + cg * 4;
        const uint32_t* cpH = cq + 64 + cg * 4;

        #pragma unroll 4
        for (int kg = 0; kg < 32; kg++) {
            uint4 aL = *(const uint4*)(zpL + kg * 128);
            uint4 aH = *(const uint4*)(zpH + kg * 128);
            uint4 bL = *(const uint4*)(cpL + kg * 128);
            uint4 bH = *(const uint4*)(cpH + kg * 128);
            int av[4] = {(int)aL.x, (int)aL.y, (int)aL.z, (int)aL.w};
            int aw[4] = {(int)aH.x, (int)aH.y, (int)aH.z, (int)aH.w};
            int bv[4] = {(int)bL.x, (int)bL.y, (int)bL.z, (int)bL.w};
            int bw[4] = {(int)bH.x, (int)bH.y, (int)bH.z, (int)bH.w};
            #pragma unroll
            for (int r = 0; r < 4; r++) {
                #pragma unroll
                for (int j = 0; j < 4; j++) {
                    aLL[r][j] = __dp4a(av[r], bv[j], aLL[r][j]);
                    aLH[r][j] = __dp4a(av[r], bw[j], aLH[r][j]);
                    aHL[r][j] = __dp4a(aw[r], bv[j], aHL[r][j]);
                    aHH[r][j] = __dp4a(aw[r], bw[j], aHH[r][j]);
                }
            }
        }

        // Epilogue: scores, running-min threshold, candidate append
        const int codeL0 = c * 128 + cg * 4;
        const int codeH0 = codeL0 + 64;
        float4 ccL4 = *(const float4*)(ccs + codeL0);
        float4 ccH4 = *(const float4*)(ccs + codeH0);
        float ccL[4] = {ccL4.x, ccL4.y, ccL4.z, ccL4.w};
        float ccH[4] = {ccH4.x, ccH4.y, ccH4.z, ccH4.w};
        #pragma unroll
        for (int r = 0; r < 4; r++) {
            float sLL[4], sLH[4], sHL[4], sHH[4];
            #pragma unroll
            for (int j = 0; j < 4; j++) {
                sLL[j] = fmaf((float)aLL[r][j], lam, ccL[j]);
                sLH[j] = fmaf((float)aLH[r][j], lam, ccH[j]);
                sHL[j] = fmaf((float)aHL[r][j], lam, ccL[j]);
                sHH[j] = fmaf((float)aHH[r][j], lam, ccH[j]);
            }
            float mL = fminf(fminf(fminf(sLL[0], sLL[1]), fminf(sLL[2], sLL[3])),
                             fminf(fminf(sLH[0], sLH[1]), fminf(sLH[2], sLH[3])));
            float mH = fminf(fminf(fminf(sHL[0], sHL[1]), fminf(sHL[2], sHL[3])),
                             fminf(fminf(sHH[0], sHH[1]), fminf(sHH[2], sHH[3])));
            #pragma unroll
            for (int k = 1; k < 16; k <<= 1) {
                mL = fminf(mL, __shfl_xor_sync(0xffffffffu, mL, k));
                mH = fminf(mH, __shfl_xor_sync(0xffffffffu, mH, k));
            }
            tminL[r] = fminf(tminL[r], mL);
            tminH[r] = fminf(tminH[r], mH);
            float thL = tminL[r] + mgL[r];
            float thH = tminH[r] + mgH[r];
            int rL = rowL + r, rH = rowH + r;
            #pragma unroll
            for (int j = 0; j < 4; j++) {
                if (sLL[j] < thL) { int p = atomicAdd(&cnt[rL], 1); if (p < CAP) cand[rL*CAP+p] = (uint16_t)(codeL0+j); }
                if (sLH[j] < thL) { int p = atomicAdd(&cnt[rL], 1); if (p < CAP) cand[rL*CAP+p] = (uint16_t)(codeH0+j); }
                if (sHL[j] < thH) { int p = atomicAdd(&cnt[rH], 1); if (p < CAP) cand[rH*CAP+p] = (uint16_t)(codeL0+j); }
                if (sHH[j] < thH) { int p = atomicAdd(&cnt[rH], 1); if (p < CAP) cand[rH*CAP+p] = (uint16_t)(codeH0+j); }
            }
        }
    }
    __syncthreads();

    // ---- Exact rescoring (zex still resident) ----
    if (tid < 128) {
        const float* zr = zex + tid * 129;
        // S_z: strictly sequential fp32 chain (matches ref jnp.sum(z*z))
        float sz = 0.f;
        for (int k = 0; k < CC; k++)
            sz = __fadd_rn(sz, __fmul_rn(zr[k], zr[k]));

        int nc = cnt[tid];
        float best = 3.4e38f;
        int   bidx = 0x7fffffff;
        if (nc <= CAP) {
            for (int i = 0; i < nc; i++) {
                int code = cand[tid * CAP + i];
                const float* cr = cb + code * CC;
                float a0 = 0.f, a1 = 0.f, a2 = 0.f, a3 = 0.f;
                #pragma unroll 8
                for (int k = 0; k < CC; k += 4) {
                    a0 = fmaf(zr[k],     cr[k],     a0);
                    a1 = fmaf(zr[k + 1], cr[k + 1], a1);
                    a2 = fmaf(zr[k + 2], cr[k + 2], a2);
                    a3 = fmaf(zr[k + 3], cr[k + 3], a3);
                }
                float gacc = (a0 + a1) + (a2 + a3);
                float d2 = __fadd_rn(__fsub_rn(sz, __fmul_rn(2.f, gacc)), ccs[code]);
                if (d2 < best || (d2 == best && code < bidx)) { best = d2; bidx = code; }
            }
        } else {
            // overflow fallback (should be ~never with rigorous margin)
            for (int code = 0; code < KK; code++) {
                const float* cr = cb + code * CC;
                float a0 = 0.f, a1 = 0.f, a2 = 0.f, a3 = 0.f;
                #pragma unroll 8
                for (int k = 0; k < CC; k += 4) {
                    a0 = fmaf(zr[k],     cr[k],     a0);
                    a1 = fmaf(zr[k + 1], cr[k + 1], a1);
                    a2 = fmaf(zr[k + 2], cr[k + 2], a2);
                    a3 = fmaf(zr[k + 3], cr[k + 3], a3);
                }
                float gacc = (a0 + a1) + (a2 + a3);
                float d2 = __fadd_rn(__fsub_rn(sz, __fmul_rn(2.f, gacc)), ccs[code]);
                if (d2 < best) { best = d2; bidx = code; }
            }
        }
        g_idx[n0 + tid] = bidx;
        out_idx_f[n0 + tid] = (float)bidx;
    }
}

// ---------------------------------------------------------------------------
// K3: gather codebook rows, write quantized, loss partials, counts.
// ---------------------------------------------------------------------------
__global__ __launch_bounds__(256)
void k_quant(const float* __restrict__ z, const float* __restrict__ cb,
             float* __restrict__ out_q) {
    __shared__ int   idx_s[64];
    __shared__ float qs[64][129];
    __shared__ double red[256];

    const int tid = threadIdx.x;
    const int n0  = blockIdx.x * 64;
    const int b   = n0 >> 12;
    const int hw0 = n0 & 4095;

    if (tid < 64) {
        int idx = g_idx[n0 + tid];
        idx_s[tid] = idx;
        atomicAdd(&g_counts[idx], 1);
    }
    __syncthreads();

    for (int g = tid; g < 64 * 128; g += 256) {
        int hw = g >> 7, k = g & 127;
        qs[hw][k] = cb[idx_s[hw] * CC + k];
    }
    __syncthreads();

    const float* zb = z     + (size_t)b * CC * HW + hw0;
    float*       ob = out_q + (size_t)b * CC * HW + hw0;
    const int hw = tid & 63;
    const int c0 = tid >> 6;

    double acc = 0.0;
    #pragma unroll 8
    for (int i = 0; i < 32; i++) {
        int c = c0 + i * 4;
        float zv = zb[c * HW + hw];
        float qv = qs[hw][c];
        ob[c * HW + hw] = __fadd_rn(zv, __fsub_rn(qv, zv));
        float d = __fsub_rn(zv, qv);
        acc += (double)d * (double)d;
    }

    red[tid] = acc;
    __syncthreads();
    #pragma unroll
    for (int s = 128; s > 0; s >>= 1) {
        if (tid < s) red[tid] += red[tid + s];
        __syncthreads();
    }
    if (tid == 0) g_partial[blockIdx.x] = red[0];
}

// ---------------------------------------------------------------------------
// K4: finalize — vq_loss and perplexity
// ---------------------------------------------------------------------------
__global__ __launch_bounds__(256)
void k_final(float* __restrict__ out) {
    __shared__ double red[256];
    const int tid = threadIdx.x;

    double a = 0.0;
    for (int i = tid; i < NN/64; i += 256) a += g_partial[i];
    red[tid] = a;
    __syncthreads();
    #pragma unroll
    for (int s = 128; s > 0; s >>= 1) {
        if (tid < s) red[tid] += red[tid + s];
        __syncthreads();
    }
    if (tid == 0) {
        double mse = red[0] / (double)Q_ELEMS;
        float m = (float)mse;
        out[OUT_SCAL_OFF + 0] = __fadd_rn(m, 0.25f * m);
    }
    __syncthreads();

    double e = 0.0;
    for (int i = tid; i < KK; i += 256) {
        float p = (float)g_counts[i] / 65536.0f;
        float term = p * logf(p + 1e-10f);
        e += (double)term;
    }
    red[tid] = e;
    __syncthreads();
    #pragma unroll
    for (int s = 128; s > 0; s >>= 1) {
        if (tid < s) red[tid] += red[tid + s];
        __syncthreads();
    }
    if (tid == 0)
        out[OUT_SCAL_OFF + 1] = expf((float)(-red[0]));
}

// ---------------------------------------------------------------------------
extern "C" void kernel_launch(void* const* d_in, const int* in_sizes, int n_in,
                              void* d_out, int out_size) {
    const float* z  = (const float*)d_in[0];  // [16,128,64,64]
    const float* cb = (const float*)d_in[1];  // [1024,128]
    float* out = (float*)d_out;               // [quantized | indices | vq | ppl]

    static bool attr_set = false;
    if (!attr_set) {
        cudaFuncSetAttribute(k_screen, cudaFuncAttributeMaxDynamicSharedMemorySize,
                             SM_DYN);
        attr_set = true;
    }

    k_prep  <<<512, 256>>>(cb);
    k_screen<<<NN / M_CTA, 256, SM_DYN>>>(z, cb, out + OUT_IDX_OFF);
    k_quant <<<NN / 64, 256>>>(z, cb, out);
    k_final <<<1, 256>>>(out);
}